// round 7
// baseline (speedup 1.0000x reference)
#include <cuda_runtime.h>
#include <cuda_bf16.h>
#include <math.h>

// Problem constants
#define Bsz   2
#define Npts  8192
#define Kn    3
#define NC    32             // candidate chunks
#define CHUNK (Npts / NC)    // 256 candidates per chunk
#define TILE  128            // smem candidate tile / threads per block
#define QPT   4              // queries per thread
#define QPB   (TILE * QPT)   // 512 queries per block
#define NQ    (Bsz * Npts)   // 16384 total queries
#define BF    4              // candidate batch (deferred-insert granularity)

// Scratch: per (query, chunk) partial top-3 (dist + idx)
__device__ float g_pd[NQ * NC * 3];
__device__ int   g_pi[NQ * NC * 3];

// Top-3 insert, strict < while scanning ascending candidate index
// == jax.lax.top_k tie-break (smaller index wins on equal distance).
__device__ __forceinline__ void insert3(float f, int cand,
                                        float& t0, float& t1, float& t2,
                                        int& i0, int& i1, int& i2)
{
    if (f < t2) {
        if (f < t0)      { t2 = t1; i2 = i1; t1 = t0; i1 = i0; t0 = f; i0 = cand; }
        else if (f < t1) { t2 = t1; i2 = i1; t1 = f;  i1 = cand; }
        else             { t2 = f;  i2 = cand; }
    }
}

// ---------------------------------------------------------------------------
// Kernel 1: partial KNN in t-space with deferred insert.
//   d = |q|^2 + |s|^2 - 2 q.s ;  t = (-2s).q + |s|^2 = d - |q|^2 (monotone).
// Candidates staged in smem as float4 {-2x,-2y,-2z,|s|^2} (one LDS.128 each).
// Inner loop processes BF=4 candidates per query: 12 FFMA + 3 FMNMX + 1 FSETP
// + 1 rarely-taken branch into a full insert3 re-inspect of the batch. The
// fast path carries NO select chains -> low instruction count, no predicated
// shifting of the top-3 state.
// blockIdx.x = query tile (512 queries), blockIdx.y = chunk (256 candidates).
// ---------------------------------------------------------------------------
__global__ __launch_bounds__(TILE) void knn_partial_kernel(
    const float* __restrict__ xyz, float* __restrict__ out)
{
    if (blockIdx.x == 0 && blockIdx.y == 0 && threadIdx.x == 0) out[0] = 0.0f;

    const int tid   = threadIdx.x;
    const int qbase = blockIdx.x * QPB;
    const int b     = qbase >> 13;            // 512 | 8192 -> one batch per block
    const float* xb = xyz + (size_t)b * Npts * 3;
    const int q0    = (qbase & (Npts - 1)) + tid;

    // Load queries + their squared norms
    float qx[QPT], qy[QPT], qz[QPT], qn[QPT];
    #pragma unroll
    for (int i = 0; i < QPT; i++) {
        const int q = q0 + i * TILE;
        qx[i] = xb[q * 3 + 0];
        qy[i] = xb[q * 3 + 1];
        qz[i] = xb[q * 3 + 2];
        qn[i] = fmaf(qx[i], qx[i], fmaf(qy[i], qy[i], qz[i] * qz[i]));
    }

    // Top-3 state in t-space
    float t0v[QPT], t1v[QPT], t2v[QPT];
    int   i0[QPT], i1[QPT], i2[QPT];
    #pragma unroll
    for (int i = 0; i < QPT; i++) {
        t0v[i] = t1v[i] = t2v[i] = INFINITY;
        i0[i] = i1[i] = i2[i] = 0x7fffffff;
    }

    __shared__ float4 sc[TILE];   // {-2x, -2y, -2z, |s|^2}

    const int cbeg = blockIdx.y * CHUNK;
    const int cend = cbeg + CHUNK;

    for (int tb = cbeg; tb < cend; tb += TILE) {
        __syncthreads();
        {
            const int j = tb + tid;
            const float x = xb[j * 3 + 0];
            const float y = xb[j * 3 + 1];
            const float z = xb[j * 3 + 2];
            const float n = fmaf(x, x, fmaf(y, y, z * z));
            sc[tid] = make_float4(-2.0f * x, -2.0f * y, -2.0f * z, n);
        }
        __syncthreads();

        #pragma unroll 4
        for (int jb = 0; jb < TILE; jb += BF) {
            // Stage BF candidates into registers (broadcast LDS.128)
            float4 c[BF];
            #pragma unroll
            for (int j = 0; j < BF; j++) c[j] = sc[jb + j];

            #pragma unroll
            for (int i = 0; i < QPT; i++) {
                float t[BF];
                #pragma unroll
                for (int j = 0; j < BF; j++) {
                    float tt = fmaf(qx[i], c[j].x, c[j].w);
                    tt = fmaf(qy[i], c[j].y, tt);
                    t[j] = fmaf(qz[i], c[j].z, tt);
                }
                // branchless batch min (FMNMX tree)
                const float bm = fminf(fminf(t[0], t[1]), fminf(t[2], t[3]));
                if (bm < t2v[i]) {
                    // Slow path (rare): ordered insert, ascending index
                    #pragma unroll
                    for (int j = 0; j < BF; j++)
                        insert3(t[j], tb + jb + j,
                                t0v[i], t1v[i], t2v[i], i0[i], i1[i], i2[i]);
                }
            }
        }
    }

    // Convert t -> d = t + |q|^2 at writeout
    const int ch = blockIdx.y;
    #pragma unroll
    for (int i = 0; i < QPT; i++) {
        const int gq   = qbase + i * TILE + tid;
        const int base = (gq * NC + ch) * 3;
        g_pd[base + 0] = t0v[i] + qn[i];
        g_pd[base + 1] = t1v[i] + qn[i];
        g_pd[base + 2] = t2v[i] + qn[i];
        g_pi[base + 0] = i0[i]; g_pi[base + 1] = i1[i]; g_pi[base + 2] = i2[i];
    }
}

// ---------------------------------------------------------------------------
// Kernel 2: merge partials (warp per query, 96 partials = 3 slots per lane)
// + gather attributes + std loss.
// ---------------------------------------------------------------------------
#define K2_THREADS 256
#define K2_WARPS   (K2_THREADS / 32)
#define NPART      (NC * 3)          // 96 partials per query
#define SLOTS      (NPART / 32)      // 3 per lane

__global__ __launch_bounds__(K2_THREADS) void merge_loss_kernel(
    const float* __restrict__ rot,  // [B,N,4]
    const float* __restrict__ scl,  // [B,N,3]
    const float* __restrict__ col,  // [B,N,45]
    const float* __restrict__ opa,  // [B,N,1]
    float* __restrict__ out)
{
    const int lane = threadIdx.x & 31;
    const int wid  = threadIdx.x >> 5;
    const int gq   = blockIdx.x * K2_WARPS + wid;
    const int b    = gq >> 13;

    // Each lane holds SLOTS=3 partial candidates (coalesced: 96 consecutive)
    float v[SLOTS]; int ix[SLOTS];
    {
        const int base = gq * NPART + lane * SLOTS;
        #pragma unroll
        for (int s = 0; s < SLOTS; s++) {
            v[s]  = g_pd[base + s];
            ix[s] = g_pi[base + s];
        }
    }

    // 3 rounds of lexicographic argmin (d, then idx) across 96 candidates.
    float nd[Kn];
    int   ni[Kn];
    #pragma unroll
    for (int r = 0; r < Kn; r++) {
        float bv = v[0]; int bi = ix[0];
        #pragma unroll
        for (int s = 1; s < SLOTS; s++)
            if (v[s] < bv || (v[s] == bv && ix[s] < bi)) { bv = v[s]; bi = ix[s]; }
        #pragma unroll
        for (int off = 16; off > 0; off >>= 1) {
            const float ov = __shfl_xor_sync(0xffffffffu, bv, off);
            const int   oi = __shfl_xor_sync(0xffffffffu, bi, off);
            if (ov < bv || (ov == bv && oi < bi)) { bv = ov; bi = oi; }
        }
        nd[r] = bv; ni[r] = bi;
        #pragma unroll
        for (int s = 0; s < SLOTS; s++)
            if (ix[s] == bi) v[s] = INFINITY;   // indices unique across partials
    }

    const int r0 = b * Npts + ni[0];
    const int r1 = b * Npts + ni[1];
    const int r2 = b * Npts + ni[2];

    float local = 0.0f;
    if (lane == 0)
        local += (nd[0] + nd[1] + nd[2]) * (1.0f / ((float)Bsz * Npts * Kn));

    // 53 channels: 0..3 rot(C=4), 4..6 scales(C=3), 7 opacity(C=1), 8..52 colors(C=45)
    for (int c = lane; c < 53; c += 32) {
        const float* bp; int C; int cc;
        if (c < 4)       { bp = rot; C = 4;  cc = c;     }
        else if (c < 7)  { bp = scl; C = 3;  cc = c - 4; }
        else if (c < 8)  { bp = opa; C = 1;  cc = 0;     }
        else             { bp = col; C = 45; cc = c - 8; }

        const float x0 = __ldg(bp + (size_t)r0 * C + cc);
        const float x1 = __ldg(bp + (size_t)r1 * C + cc);
        const float x2 = __ldg(bp + (size_t)r2 * C + cc);

        const float m  = (x0 + x1 + x2) * (1.0f / 3.0f);
        const float e0 = x0 - m, e1 = x1 - m, e2 = x2 - m;
        const float var = fmaf(e0, e0, fmaf(e1, e1, e2 * e2)) * 0.5f;  // ddof=1
        local += sqrtf(var) * (1.0f / ((float)Bsz * Npts * (float)C));
    }

    #pragma unroll
    for (int off = 16; off > 0; off >>= 1)
        local += __shfl_xor_sync(0xffffffffu, local, off);

    __shared__ float red[K2_WARPS];
    if (lane == 0) red[wid] = local;
    __syncthreads();

    if (threadIdx.x < K2_WARPS) {
        float s = red[threadIdx.x];
        #pragma unroll
        for (int off = K2_WARPS / 2; off > 0; off >>= 1)
            s += __shfl_xor_sync((1u << K2_WARPS) - 1u, s, off);
        if (threadIdx.x == 0) atomicAdd(out, s);
    }
}

// ---------------------------------------------------------------------------
extern "C" void kernel_launch(void* const* d_in, const int* in_sizes, int n_in,
                              void* d_out, int out_size)
{
    const float* xyz = (const float*)d_in[0];
    const float* rot = (const float*)d_in[1];
    const float* scl = (const float*)d_in[2];
    const float* col = (const float*)d_in[3];
    const float* opa = (const float*)d_in[4];
    float* out = (float*)d_out;

    dim3 g1(NQ / QPB, NC);   // (32, 32) = 1024 blocks
    knn_partial_kernel<<<g1, TILE>>>(xyz, out);

    merge_loss_kernel<<<NQ / K2_WARPS, K2_THREADS>>>(rot, scl, col, opa, out);
}

// round 8
// speedup vs baseline: 1.7590x; 1.7590x over previous
#include <cuda_runtime.h>
#include <cuda_bf16.h>
#include <math.h>

// Problem constants
#define Bsz     2
#define Npts    8192
#define Kn      3
#define NQ      (Bsz * Npts)
#define THREADS 128
#define WARPS   (THREADS / 32)     // 4 warps per block
#define G       4                  // queries per warp
#define QPB     (WARPS * G)        // 16 queries per block
#define TILE_C  1024               // candidates per smem tile
#define NTILES  (Npts / TILE_C)    // 8 tiles

#define FULLMASK 0xffffffffu

// Top-3 insert, strict < (ascending candidate order == jax.lax.top_k tie-break)
__device__ __forceinline__ void insert3(float f, int cand,
                                        float& t0, float& t1, float& t2,
                                        int& i0, int& i1, int& i2)
{
    if (f < t2) {
        if (f < t0)      { t2 = t1; i2 = i1; t1 = t0; i1 = i0; t0 = f; i0 = cand; }
        else if (f < t1) { t2 = t1; i2 = i1; t1 = f;  i1 = cand; }
        else             { t2 = f;  i2 = cand; }
    }
}

__global__ void zero_out_kernel(float* out) { out[0] = 0.0f; }

// ---------------------------------------------------------------------------
// Fused KNN + loss. Warp owns G=4 queries; lanes scan 32 distinct candidates
// per step. t-space: t = (-2s).q + |s|^2 = d - |q|^2 (monotone per query).
// Fast path: 12 FFMA + 4 FSETP + 1 ballot per 128 pairs. Slow path (warp-
// uniform, rare): per-query ballot, iterate set bits ascending (== ascending
// candidate index), shuffle-broadcast t, replicated insert3 -> EXACT
// sequential strict-< semantics. Prologue: first 32 candidates via 3 rounds
// of warp lexicographic argmin (t, idx).
// ---------------------------------------------------------------------------
__global__ __launch_bounds__(THREADS) void knnreg_kernel(
    const float* __restrict__ xyz,   // [B,N,3]
    const float* __restrict__ rot,   // [B,N,4]
    const float* __restrict__ scl,   // [B,N,3]
    const float* __restrict__ col,   // [B,N,45]
    const float* __restrict__ opa,   // [B,N,1]
    float* __restrict__ out)
{
    const int tid  = threadIdx.x;
    const int lane = tid & 31;
    const int wid  = tid >> 5;
    const int qblk = blockIdx.x * QPB;          // first global query of block
    const int b    = qblk >> 13;                // batch (QPB=16 | 8192)
    const float* xb = xyz + (size_t)b * Npts * 3;
    const int qw   = (qblk & (Npts - 1)) + wid * G;   // warp's first local query

    // Load the warp's 4 queries (same addresses across lanes -> broadcast)
    float qx[G], qy[G], qz[G], qn[G];
    #pragma unroll
    for (int g = 0; g < G; g++) {
        const int q = qw + g;
        qx[g] = xb[q * 3 + 0];
        qy[g] = xb[q * 3 + 1];
        qz[g] = xb[q * 3 + 2];
        qn[g] = fmaf(qx[g], qx[g], fmaf(qy[g], qy[g], qz[g] * qz[g]));
    }

    float t0[G], t1[G], t2[G];
    int   i0[G], i1[G], i2[G];

    __shared__ float4 sc[TILE_C];    // {-2x, -2y, -2z, |s|^2}
    __shared__ float  red[WARPS];

    // ---- stage tile 0 ----
    for (int k = tid; k < TILE_C; k += THREADS) {
        const int j = k;
        const float x = xb[j * 3 + 0];
        const float y = xb[j * 3 + 1];
        const float z = xb[j * 3 + 2];
        sc[k] = make_float4(-2.0f * x, -2.0f * y, -2.0f * z,
                            fmaf(x, x, fmaf(y, y, z * z)));
    }
    __syncthreads();

    // ---- prologue: candidates 0..31 via warp lex-argmin (exact) ----
    {
        const float4 c = sc[lane];
        #pragma unroll
        for (int g = 0; g < G; g++) {
            float t = fmaf(qx[g], c.x, c.w);
            t = fmaf(qy[g], c.y, t);
            t = fmaf(qz[g], c.z, t);
            float v = t; int iv = lane;
            float rt[Kn]; int ri[Kn];
            #pragma unroll
            for (int r = 0; r < Kn; r++) {
                float bv = v; int bi = iv;
                #pragma unroll
                for (int off = 16; off > 0; off >>= 1) {
                    const float ov = __shfl_xor_sync(FULLMASK, bv, off);
                    const int   oi = __shfl_xor_sync(FULLMASK, bi, off);
                    if (ov < bv || (ov == bv && oi < bi)) { bv = ov; bi = oi; }
                }
                rt[r] = bv; ri[r] = bi;
                if (iv == bi) v = INFINITY;
            }
            t0[g] = rt[0]; t1[g] = rt[1]; t2[g] = rt[2];
            i0[g] = ri[0]; i1[g] = ri[1]; i2[g] = ri[2];
        }
    }

    // ---- main scan ----
    for (int tile = 0; tile < NTILES; tile++) {
        if (tile > 0) {
            __syncthreads();
            const int base = tile * TILE_C;
            for (int k = tid; k < TILE_C; k += THREADS) {
                const int j = base + k;
                const float x = xb[j * 3 + 0];
                const float y = xb[j * 3 + 1];
                const float z = xb[j * 3 + 2];
                sc[k] = make_float4(-2.0f * x, -2.0f * y, -2.0f * z,
                                    fmaf(x, x, fmaf(y, y, z * z)));
            }
            __syncthreads();
        }

        const int sbeg = (tile == 0) ? 32 : 0;
        const int tbase = tile * TILE_C;
        for (int s = sbeg; s < TILE_C; s += 32) {
            const float4 c = sc[s + lane];
            float tg[G];
            #pragma unroll
            for (int g = 0; g < G; g++) {
                float t = fmaf(qx[g], c.x, c.w);
                t = fmaf(qy[g], c.y, t);
                tg[g] = fmaf(qz[g], c.z, t);
            }
            const bool p = (tg[0] < t2[0]) | (tg[1] < t2[1])
                         | (tg[2] < t2[2]) | (tg[3] < t2[3]);
            const unsigned bal = __ballot_sync(FULLMASK, p);
            if (bal) {
                const int cb = tbase + s;
                #pragma unroll
                for (int g = 0; g < G; g++) {
                    unsigned bg = __ballot_sync(FULLMASK, tg[g] < t2[g]);
                    while (bg) {
                        const int l = __ffs(bg) - 1;
                        bg &= bg - 1;
                        const float tv = __shfl_sync(FULLMASK, tg[g], l);
                        insert3(tv, cb + l,
                                t0[g], t1[g], t2[g], i0[g], i1[g], i2[g]);
                    }
                }
            }
        }
    }

    // ---- fused loss phase ----
    float local = 0.0f;

    #pragma unroll
    for (int g = 0; g < G; g++) {
        // distance term: d_r = t_r + |q|^2
        if (lane == 0) {
            local += ((t0[g] + qn[g]) + (t1[g] + qn[g]) + (t2[g] + qn[g]))
                     * (1.0f / ((float)Bsz * Npts * Kn));
        }

        const int r0 = b * Npts + i0[g];
        const int r1 = b * Npts + i1[g];
        const int r2 = b * Npts + i2[g];

        // 53 channels: 0..3 rot(C=4), 4..6 scales(C=3), 7 opacity(C=1), 8..52 colors(C=45)
        for (int c = lane; c < 53; c += 32) {
            const float* bp; int C; int cc;
            if (c < 4)       { bp = rot; C = 4;  cc = c;     }
            else if (c < 7)  { bp = scl; C = 3;  cc = c - 4; }
            else if (c < 8)  { bp = opa; C = 1;  cc = 0;     }
            else             { bp = col; C = 45; cc = c - 8; }

            const float x0 = __ldg(bp + (size_t)r0 * C + cc);
            const float x1 = __ldg(bp + (size_t)r1 * C + cc);
            const float x2 = __ldg(bp + (size_t)r2 * C + cc);

            const float m  = (x0 + x1 + x2) * (1.0f / 3.0f);
            const float e0 = x0 - m, e1 = x1 - m, e2 = x2 - m;
            const float var = fmaf(e0, e0, fmaf(e1, e1, e2 * e2)) * 0.5f; // ddof=1
            local += sqrtf(var) * (1.0f / ((float)Bsz * Npts * (float)C));
        }
    }

    // warp reduce
    #pragma unroll
    for (int off = 16; off > 0; off >>= 1)
        local += __shfl_xor_sync(FULLMASK, local, off);

    __syncthreads();              // sc reads done before red reuse (paranoia)
    if (lane == 0) red[wid] = local;
    __syncthreads();

    if (tid == 0) {
        float s = 0.0f;
        #pragma unroll
        for (int w = 0; w < WARPS; w++) s += red[w];
        atomicAdd(out, s);
    }
}

// ---------------------------------------------------------------------------
extern "C" void kernel_launch(void* const* d_in, const int* in_sizes, int n_in,
                              void* d_out, int out_size)
{
    const float* xyz = (const float*)d_in[0];
    const float* rot = (const float*)d_in[1];
    const float* scl = (const float*)d_in[2];
    const float* col = (const float*)d_in[3];
    const float* opa = (const float*)d_in[4];
    float* out = (float*)d_out;

    zero_out_kernel<<<1, 1>>>(out);
    knnreg_kernel<<<NQ / QPB, THREADS>>>(xyz, rot, scl, col, opa, out);
}